// round 4
// baseline (speedup 1.0000x reference)
#include <cuda_runtime.h>
#include <math.h>

#define N_TOK   4096
#define H_DIM   128
#define NH      8
#define HD      16
#define FF_DIM  256
#define L_LAYER 4
#define LAT_DIM 16
#define CAP     128

// ---------------- scratch (static device globals; no runtime alloc) ----------------
__device__ __align__(256) float g_x   [N_TOK * H_DIM];
__device__ __align__(256) float g_qkv [N_TOK * 3 * H_DIM];
__device__ __align__(256) float g_attn[N_TOK * H_DIM];
__device__ __align__(256) float g_tmp [N_TOK * FF_DIM];
__device__ __align__(256) int   g_nbr [N_TOK * CAP];
__device__ __align__(256) int   g_ncnt[N_TOK];

// ---------------- neighbor list build (eta/phi fused, smem-staged) ----------------
// 256 threads: 8 warps = 8 queries per block; all 4096 eta/phi staged in smem.
__global__ __launch_bounds__(256)
void nbr_kernel(const float* __restrict__ x_raw) {
    __shared__ float se[N_TOK];
    __shared__ float sp[N_TOK];
    const int tid = threadIdx.x;
    #pragma unroll
    for (int t = 0; t < N_TOK / 256; t++) {
        int i = tid + t * 256;
        se[i] = x_raw[i * 16 + 1] * 5.24f   + (-2.62f);
        sp[i] = x_raw[i * 16 + 2] * 6.2832f + (-3.1416f);
    }
    __syncthreads();

    const int lane = tid & 31;
    const int q    = blockIdx.x * 8 + (tid >> 5);
    const float eq = se[q], pq = sp[q];
    int cnt = 0;
    for (int k = lane; k < N_TOK; k += 32) {
        float de = eq - se[k];
        float dp = pq - sp[k];
        dp -= 6.28318530718f * rintf(dp * 0.159154943092f);
        bool hit = (de * de + dp * dp) <= 0.04f;
        unsigned mask = __ballot_sync(0xffffffffu, hit);
        if (hit) {
            int off = cnt + __popc(mask & ((1u << lane) - 1u));
            if (off < CAP) g_nbr[q * CAP + off] = k;
        }
        cnt += __popc(mask);
    }
    if (lane == 0) g_ncnt[q] = min(cnt, CAP);
}

// ---------------- plain GEMM: C = A(NxK)@W(MxK)^T + bias (+res)(relu?) -------------
// BM=32, BN=64, BK=16, 128 threads, 4x4 outputs/thread. K multiple of 16, M of 64.
#define PM 32
#define PN 64
#define PK 16

__global__ __launch_bounds__(128)
void gemm3_kernel(const float* __restrict__ A, const float* __restrict__ W,
                  const float* __restrict__ bias, const float* __restrict__ res,
                  float* __restrict__ C, int M, int K, int relu) {
    __shared__ __align__(16) float As[PK][36];
    __shared__ __align__(16) float Ws[PK][68];

    const int tid  = threadIdx.x;
    const int row0 = blockIdx.x * PM;
    const int col0 = blockIdx.y * PN;
    const int tx   = tid & 15;    // 4 cols each
    const int ty   = tid >> 4;    // 4 rows each

    float acc[4][4];
    #pragma unroll
    for (int i = 0; i < 4; i++)
        #pragma unroll
        for (int j = 0; j < 4; j++) acc[i][j] = 0.f;

    for (int k0 = 0; k0 < K; k0 += PK) {
        {   // A chunk: 32 rows x 16 k = 128 float4, 1 per thread
            int r  = tid >> 2;
            int kq = (tid & 3) << 2;
            float4 v = *(const float4*)(A + (size_t)(row0 + r) * K + k0 + kq);
            As[kq + 0][r] = v.x; As[kq + 1][r] = v.y;
            As[kq + 2][r] = v.z; As[kq + 3][r] = v.w;
        }
        #pragma unroll
        for (int t = 0; t < 2; t++) {  // W chunk: 64 rows x 16 k = 256 float4
            int i  = tid + t * 128;
            int c  = i >> 2;
            int kq = (i & 3) << 2;
            float4 v = *(const float4*)(W + (size_t)(col0 + c) * K + k0 + kq);
            Ws[kq + 0][c] = v.x; Ws[kq + 1][c] = v.y;
            Ws[kq + 2][c] = v.z; Ws[kq + 3][c] = v.w;
        }
        __syncthreads();
        #pragma unroll
        for (int k = 0; k < PK; k++) {
            float a[4], b[4];
            *(float4*)a = *(const float4*)&As[k][ty * 4];
            *(float4*)b = *(const float4*)&Ws[k][tx * 4];
            #pragma unroll
            for (int i = 0; i < 4; i++)
                #pragma unroll
                for (int j = 0; j < 4; j++)
                    acc[i][j] += a[i] * b[j];
        }
        __syncthreads();
    }

    #pragma unroll
    for (int i = 0; i < 4; i++) {
        int gr = row0 + ty * 4 + i;
        #pragma unroll
        for (int j = 0; j < 4; j++) {
            int gm = col0 + tx * 4 + j;
            float v = acc[i][j] + bias[gm];
            if (res)  v += res[(size_t)gr * M + gm];
            if (relu) v = fmaxf(v, 0.f);
            C[(size_t)gr * M + gm] = v;
        }
    }
}

// ---------------- fused LayerNorm + GEMM: C = LN(A)@W^T + bias (relu?) -------------
// A is Nx128 (K==H==128). BM=32 rows, BN=64 cols, 128 threads.
__global__ __launch_bounds__(128)
void gemm_ln_kernel(const float* __restrict__ A, const float* __restrict__ W,
                    const float* __restrict__ lnS, const float* __restrict__ lnB,
                    const float* __restrict__ bias, float* __restrict__ C,
                    int M, int relu) {
    __shared__ __align__(16) float As[H_DIM][36];   // transposed, full K
    __shared__ __align__(16) float Ws[16][68];
    __shared__ float sS[H_DIM], sB[H_DIM];
    __shared__ float sMean[PM], sInv[PM];

    const int tid  = threadIdx.x;
    const int row0 = blockIdx.x * PM;
    const int col0 = blockIdx.y * PN;

    // load LN params
    sS[tid] = lnS[tid];
    sB[tid] = lnB[tid];

    // load A tile 32x128 transposed: 1024 float4, 8/thread
    #pragma unroll
    for (int t = 0; t < 8; t++) {
        int i   = tid + t * 128;
        int r   = i >> 5;
        int kq4 = i & 31;
        float4 v = *(const float4*)(A + (size_t)(row0 + r) * H_DIM + kq4 * 4);
        int k = kq4 * 4;
        As[k + 0][r] = v.x; As[k + 1][r] = v.y;
        As[k + 2][r] = v.z; As[k + 3][r] = v.w;
    }
    __syncthreads();

    // row stats: 4 threads per row, each 32 k's
    {
        int r = tid >> 2;
        int q = tid & 3;
        float s = 0.f, s2 = 0.f;
        #pragma unroll
        for (int k = 0; k < 32; k++) {
            float v = As[q * 32 + k][r];
            s += v; s2 += v * v;
        }
        s  += __shfl_xor_sync(0xffffffffu, s, 1);
        s  += __shfl_xor_sync(0xffffffffu, s, 2);
        s2 += __shfl_xor_sync(0xffffffffu, s2, 1);
        s2 += __shfl_xor_sync(0xffffffffu, s2, 2);
        if (q == 0) {
            float mean = s * (1.f / 128.f);
            float var  = s2 * (1.f / 128.f) - mean * mean;
            sMean[r] = mean;
            sInv[r]  = rsqrtf(var + 1e-5f);
        }
    }
    __syncthreads();

    // normalize in smem
    #pragma unroll
    for (int t = 0; t < 8; t++) {
        int i   = tid + t * 128;
        int r   = i >> 5;
        int k   = (i & 31) * 4;
        float mean = sMean[r], inv = sInv[r];
        #pragma unroll
        for (int u = 0; u < 4; u++) {
            float v = As[k + u][r];
            As[k + u][r] = (v - mean) * inv * sS[k + u] + sB[k + u];
        }
    }
    __syncthreads();

    const int tx = tid & 15;
    const int ty = tid >> 4;
    float acc[4][4];
    #pragma unroll
    for (int i = 0; i < 4; i++)
        #pragma unroll
        for (int j = 0; j < 4; j++) acc[i][j] = 0.f;

    for (int k0 = 0; k0 < H_DIM; k0 += 16) {
        #pragma unroll
        for (int t = 0; t < 2; t++) {
            int i  = tid + t * 128;
            int c  = i >> 2;
            int kq = (i & 3) << 2;
            float4 v = *(const float4*)(W + (size_t)(col0 + c) * H_DIM + k0 + kq);
            Ws[kq + 0][c] = v.x; Ws[kq + 1][c] = v.y;
            Ws[kq + 2][c] = v.z; Ws[kq + 3][c] = v.w;
        }
        __syncthreads();
        #pragma unroll
        for (int k = 0; k < 16; k++) {
            float a[4], b[4];
            *(float4*)a = *(const float4*)&As[k0 + k][ty * 4];
            *(float4*)b = *(const float4*)&Ws[k][tx * 4];
            #pragma unroll
            for (int i = 0; i < 4; i++)
                #pragma unroll
                for (int j = 0; j < 4; j++)
                    acc[i][j] += a[i] * b[j];
        }
        __syncthreads();
    }

    #pragma unroll
    for (int i = 0; i < 4; i++) {
        int gr = row0 + ty * 4 + i;
        #pragma unroll
        for (int j = 0; j < 4; j++) {
            int gm = col0 + tx * 4 + j;
            float v = acc[i][j] + bias[gm];
            if (relu) v = fmaxf(v, 0.f);
            C[(size_t)gr * M + gm] = v;
        }
    }
}

// ---------------- sparse attention: one thread per (query, head) ----------------
__global__ __launch_bounds__(256)
void attn_sparse_kernel(const float* __restrict__ qkv, float* __restrict__ o) {
    int gid = blockIdx.x * 256 + threadIdx.x;
    int q = gid >> 3;
    int h = gid & 7;

    const float* qp = qkv + (size_t)q * 384 + h * HD;
    float4 q0 = *(const float4*)(qp);
    float4 q1 = *(const float4*)(qp + 4);
    float4 q2 = *(const float4*)(qp + 8);
    float4 q3 = *(const float4*)(qp + 12);

    int cnt = g_ncnt[q];
    const int* nb = &g_nbr[q * CAP];

    float m = -1e30f, l = 0.f;
    float acc[HD];
    #pragma unroll
    for (int d = 0; d < HD; d++) acc[d] = 0.f;

    for (int j = 0; j < cnt; j++) {
        int kidx = nb[j];
        const float* kp = qkv + (size_t)kidx * 384 + 128 + h * HD;
        float4 k0 = *(const float4*)(kp);
        float4 k1 = *(const float4*)(kp + 4);
        float4 k2 = *(const float4*)(kp + 8);
        float4 k3 = *(const float4*)(kp + 12);
        float s = q0.x * k0.x + q0.y * k0.y + q0.z * k0.z + q0.w * k0.w
                + q1.x * k1.x + q1.y * k1.y + q1.z * k1.z + q1.w * k1.w
                + q2.x * k2.x + q2.y * k2.y + q2.z * k2.z + q2.w * k2.w
                + q3.x * k3.x + q3.y * k3.y + q3.z * k3.z + q3.w * k3.w;
        s *= 0.25f;
        float mnew = fmaxf(m, s);
        float corr = __expf(m - mnew);
        float e    = __expf(s - mnew);
        l = l * corr + e;
        const float* vp = kp + 128;
        float4 v0 = *(const float4*)(vp);
        float4 v1 = *(const float4*)(vp + 4);
        float4 v2 = *(const float4*)(vp + 8);
        float4 v3 = *(const float4*)(vp + 12);
        acc[0]  = acc[0]  * corr + e * v0.x;  acc[1]  = acc[1]  * corr + e * v0.y;
        acc[2]  = acc[2]  * corr + e * v0.z;  acc[3]  = acc[3]  * corr + e * v0.w;
        acc[4]  = acc[4]  * corr + e * v1.x;  acc[5]  = acc[5]  * corr + e * v1.y;
        acc[6]  = acc[6]  * corr + e * v1.z;  acc[7]  = acc[7]  * corr + e * v1.w;
        acc[8]  = acc[8]  * corr + e * v2.x;  acc[9]  = acc[9]  * corr + e * v2.y;
        acc[10] = acc[10] * corr + e * v2.z;  acc[11] = acc[11] * corr + e * v2.w;
        acc[12] = acc[12] * corr + e * v3.x;  acc[13] = acc[13] * corr + e * v3.y;
        acc[14] = acc[14] * corr + e * v3.z;  acc[15] = acc[15] * corr + e * v3.w;
        m = mnew;
    }

    float inv = 1.f / l;
    float* op = o + (size_t)q * H_DIM + h * HD;
    #pragma unroll
    for (int d = 0; d < HD; d++) op[d] = acc[d] * inv;
}

// ---------------- fused heads: lat + beta + epilogue, 32 rows per 128-thr block ----
__global__ __launch_bounds__(128)
void head_kernel(const float* __restrict__ x,
                 const float* __restrict__ lat1_w, const float* __restrict__ lat1_b,
                 const float* __restrict__ lat2_w, const float* __restrict__ lat2_b,
                 const float* __restrict__ b1_w,   const float* __restrict__ b1_b,
                 const float* __restrict__ b2_w,   const float* __restrict__ b2_b,
                 float* __restrict__ out) {
    __shared__ float Xs[32][132];
    __shared__ float H1[32][132];
    __shared__ float Lt[32][20];
    __shared__ float B1[32][68];

    const int tid  = threadIdx.x;
    const int row0 = blockIdx.x * 32;
    const int r    = tid >> 2;
    const int q    = tid & 3;

    // load x tile row-major
    #pragma unroll
    for (int t = 0; t < 8; t++) {
        int i  = tid + t * 128;
        int rr = i >> 5;
        int c  = (i & 31) * 4;
        float4 v = *(const float4*)(x + (size_t)(row0 + rr) * H_DIM + c);
        Xs[rr][c] = v.x; Xs[rr][c + 1] = v.y; Xs[rr][c + 2] = v.z; Xs[rr][c + 3] = v.w;
    }
    __syncthreads();

    // h1 = relu(x @ lat1^T + lat1_b): cols q*32..q*32+31
    #pragma unroll 1
    for (int c = 0; c < 32; c++) {
        int col = q * 32 + c;
        const float* wp = lat1_w + (size_t)col * H_DIM;
        float s = lat1_b[col];
        #pragma unroll 8
        for (int k = 0; k < H_DIM; k++) s += Xs[r][k] * wp[k];
        H1[r][col] = fmaxf(s, 0.f);
    }
    // b1h = relu(x @ b1^T + b1_b): cols q*16..q*16+15
    #pragma unroll 1
    for (int c = 0; c < 16; c++) {
        int col = q * 16 + c;
        const float* wp = b1_w + (size_t)col * H_DIM;
        float s = b1_b[col];
        #pragma unroll 8
        for (int k = 0; k < H_DIM; k++) s += Xs[r][k] * wp[k];
        B1[r][col] = fmaxf(s, 0.f);
    }
    __syncthreads();

    // lat = h1 @ lat2^T + lat2_b: cols q*4..q*4+3
    #pragma unroll
    for (int c = 0; c < 4; c++) {
        int col = q * 4 + c;
        const float* wp = lat2_w + (size_t)col * H_DIM;
        float s = lat2_b[col];
        #pragma unroll 8
        for (int k = 0; k < H_DIM; k++) s += H1[r][k] * wp[k];
        Lt[r][col] = s;
    }
    __syncthreads();

    // tail: one thread per row
    if (tid < 32) {
        int rr = tid;
        float s = b2_b[0];
        #pragma unroll 8
        for (int k = 0; k < 64; k++) s += B1[rr][k] * b2_w[k];
        float bb = 1.f / (1.f + __expf(-s));
        bb = fminf(fmaxf(bb, 1e-6f), 1.f - 1e-6f);
        out[row0 + rr] = bb;

        float nn = 0.f;
        #pragma unroll
        for (int d = 0; d < LAT_DIM; d++) nn += Lt[rr][d] * Lt[rr][d];
        float inv = 1.f / fmaxf(sqrtf(nn), 1e-12f);
        #pragma unroll
        for (int d = 0; d < LAT_DIM; d++)
            out[N_TOK + (size_t)(row0 + rr) * LAT_DIM + d] = Lt[rr][d] * inv;
    }
}

// ---------------- host orchestration ----------------
extern "C" void kernel_launch(void* const* d_in, const int* in_sizes, int n_in,
                              void* d_out, int out_size) {
    const float* x_raw  = (const float*)d_in[0];
    const float* in_w   = (const float*)d_in[2];
    const float* in_b   = (const float*)d_in[3];
    const float* ln1_s  = (const float*)d_in[4];
    const float* ln1_b  = (const float*)d_in[5];
    const float* qkv_w  = (const float*)d_in[6];
    const float* qkv_b  = (const float*)d_in[7];
    const float* ao_w   = (const float*)d_in[8];
    const float* ao_b   = (const float*)d_in[9];
    const float* ln2_s  = (const float*)d_in[10];
    const float* ln2_b  = (const float*)d_in[11];
    const float* f1_w   = (const float*)d_in[12];
    const float* f1_b   = (const float*)d_in[13];
    const float* f2_w   = (const float*)d_in[14];
    const float* f2_b   = (const float*)d_in[15];
    const float* lat1_w = (const float*)d_in[16];
    const float* lat1_b = (const float*)d_in[17];
    const float* lat2_w = (const float*)d_in[18];
    const float* lat2_b = (const float*)d_in[19];
    const float* b1_w   = (const float*)d_in[20];
    const float* b1_b   = (const float*)d_in[21];
    const float* b2_w   = (const float*)d_in[22];
    const float* b2_b   = (const float*)d_in[23];

    float *x, *qkv, *attn, *tmp;
    cudaGetSymbolAddress((void**)&x,    g_x);
    cudaGetSymbolAddress((void**)&qkv,  g_qkv);
    cudaGetSymbolAddress((void**)&attn, g_attn);
    cudaGetSymbolAddress((void**)&tmp,  g_tmp);

    dim3 blk(128);

    nbr_kernel<<<N_TOK / 8, 256>>>(x_raw);

    // input projection: x = x_raw @ in_w^T + in_b   (K=16, M=128)
    gemm3_kernel<<<dim3(N_TOK / PM, H_DIM / PN), blk>>>(
        x_raw, in_w, in_b, nullptr, x, H_DIM, 16, 0);

    for (int l = 0; l < L_LAYER; l++) {
        // LN1 + QKV fused
        gemm_ln_kernel<<<dim3(N_TOK / PM, (3 * H_DIM) / PN), blk>>>(
            x, qkv_w + (size_t)l * 3 * H_DIM * H_DIM,
            ln1_s + l * H_DIM, ln1_b + l * H_DIM,
            qkv_b + l * 3 * H_DIM, qkv, 3 * H_DIM, 0);
        // sparse attention
        attn_sparse_kernel<<<(N_TOK * NH) / 256, 256>>>(qkv, attn);
        // attn out proj + residual
        gemm3_kernel<<<dim3(N_TOK / PM, H_DIM / PN), blk>>>(
            attn, ao_w + (size_t)l * H_DIM * H_DIM, ao_b + l * H_DIM,
            x, x, H_DIM, H_DIM, 0);
        // LN2 + FF1 fused (relu)
        gemm_ln_kernel<<<dim3(N_TOK / PM, FF_DIM / PN), blk>>>(
            x, f1_w + (size_t)l * FF_DIM * H_DIM,
            ln2_s + l * H_DIM, ln2_b + l * H_DIM,
            f1_b + l * FF_DIM, tmp, FF_DIM, 1);
        // FF2 + residual
        gemm3_kernel<<<dim3(N_TOK / PM, H_DIM / PN), blk>>>(
            tmp, f2_w + (size_t)l * H_DIM * FF_DIM, f2_b + l * H_DIM,
            x, x, H_DIM, FF_DIM, 0);
    }

    head_kernel<<<N_TOK / 32, 128>>>(x, lat1_w, lat1_b, lat2_w, lat2_b,
                                     b1_w, b1_b, b2_w, b2_b, (float*)d_out);
}

// round 5
// speedup vs baseline: 1.1845x; 1.1845x over previous
#include <cuda_runtime.h>
#include <math.h>

#define N_TOK   4096
#define H_DIM   128
#define NH      8
#define HD      16
#define FF_DIM  256
#define L_LAYER 4
#define LAT_DIM 16
#define CAP     128

// ---------------- scratch (static device globals; no runtime alloc) ----------------
__device__ __align__(256) float g_x   [N_TOK * H_DIM];
__device__ __align__(256) float g_xn  [N_TOK * H_DIM];
__device__ __align__(256) float g_qkv [N_TOK * 3 * H_DIM];
__device__ __align__(256) float g_attn[N_TOK * H_DIM];
__device__ __align__(256) float g_tmp [N_TOK * FF_DIM];
__device__ __align__(256) int   g_nbr [N_TOK * CAP];
__device__ __align__(256) int   g_ncnt[N_TOK];

// ---------------- neighbor list build (eta/phi fused, smem-staged) ----------------
__global__ __launch_bounds__(256)
void nbr_kernel(const float* __restrict__ x_raw) {
    __shared__ float se[N_TOK];
    __shared__ float sp[N_TOK];
    const int tid = threadIdx.x;
    #pragma unroll
    for (int t = 0; t < N_TOK / 256; t++) {
        int i = tid + t * 256;
        se[i] = x_raw[i * 16 + 1] * 5.24f   + (-2.62f);
        sp[i] = x_raw[i * 16 + 2] * 6.2832f + (-3.1416f);
    }
    __syncthreads();

    const int lane = tid & 31;
    const int q    = blockIdx.x * 8 + (tid >> 5);
    const float eq = se[q], pq = sp[q];
    int cnt = 0;
    for (int k = lane; k < N_TOK; k += 32) {
        float de = eq - se[k];
        float dp = pq - sp[k];
        dp -= 6.28318530718f * rintf(dp * 0.159154943092f);
        bool hit = (de * de + dp * dp) <= 0.04f;
        unsigned mask = __ballot_sync(0xffffffffu, hit);
        if (hit) {
            int off = cnt + __popc(mask & ((1u << lane) - 1u));
            if (off < CAP) g_nbr[q * CAP + off] = k;
        }
        cnt += __popc(mask);
    }
    if (lane == 0) g_ncnt[q] = min(cnt, CAP);
}

// ---------------- register-tiled GEMM (round-3 known good): 64x64x16 ----------------
#define GM 64
#define GN 64
#define GK 16
#define GMP 68   // 272B row pitch, 16B multiple

__global__ __launch_bounds__(128)
void gemm2_kernel(const float* __restrict__ A, const float* __restrict__ W,
                  const float* __restrict__ bias, const float* __restrict__ res,
                  float* __restrict__ C, int N, int M, int K, int relu) {
    __shared__ __align__(16) float As[GK][GMP];
    __shared__ __align__(16) float Ws[GK][GMP];

    const int tid  = threadIdx.x;
    const int row0 = blockIdx.x * GM;
    const int col0 = blockIdx.y * GN;
    const int tx   = tid & 15;
    const int ty   = tid >> 4;

    float acc[8][4];
    #pragma unroll
    for (int i = 0; i < 8; i++)
        #pragma unroll
        for (int j = 0; j < 4; j++) acc[i][j] = 0.f;

    for (int k0 = 0; k0 < K; k0 += GK) {
        #pragma unroll
        for (int t = 0; t < 2; t++) {
            int i = tid + t * 128;
            int r = i >> 2, kq = (i & 3) << 2;
            int gr = row0 + r;
            float4 v = make_float4(0.f, 0.f, 0.f, 0.f);
            if (gr < N) v = *(const float4*)(A + (size_t)gr * K + k0 + kq);
            As[kq + 0][r] = v.x; As[kq + 1][r] = v.y;
            As[kq + 2][r] = v.z; As[kq + 3][r] = v.w;
        }
        #pragma unroll
        for (int t = 0; t < 2; t++) {
            int i = tid + t * 128;
            int r = i >> 2, kq = (i & 3) << 2;
            int gm = col0 + r;
            float4 v = make_float4(0.f, 0.f, 0.f, 0.f);
            if (gm < M) v = *(const float4*)(W + (size_t)gm * K + k0 + kq);
            Ws[kq + 0][r] = v.x; Ws[kq + 1][r] = v.y;
            Ws[kq + 2][r] = v.z; Ws[kq + 3][r] = v.w;
        }
        __syncthreads();
        #pragma unroll
        for (int k = 0; k < GK; k++) {
            float a[8], b[4];
            *(float4*)(a)     = *(const float4*)&As[k][ty * 8];
            *(float4*)(a + 4) = *(const float4*)&As[k][ty * 8 + 4];
            *(float4*)(b)     = *(const float4*)&Ws[k][tx * 4];
            #pragma unroll
            for (int i = 0; i < 8; i++)
                #pragma unroll
                for (int j = 0; j < 4; j++)
                    acc[i][j] += a[i] * b[j];
        }
        __syncthreads();
    }

    #pragma unroll
    for (int i = 0; i < 8; i++) {
        int gr = row0 + ty * 8 + i;
        if (gr >= N) continue;
        #pragma unroll
        for (int j = 0; j < 4; j++) {
            int gm = col0 + tx * 4 + j;
            if (gm >= M) continue;
            float v = acc[i][j] + bias[gm];
            if (res)  v += res[(size_t)gr * M + gm];
            if (relu) v = fmaxf(v, 0.f);
            C[(size_t)gr * M + gm] = v;
        }
    }
}

// ---------------- LayerNorm: one row per block (128 threads) ----------------
__global__ __launch_bounds__(128)
void ln_kernel(const float* __restrict__ x, const float* __restrict__ sc,
               const float* __restrict__ bi, float* __restrict__ out) {
    const int row = blockIdx.x;
    const int t   = threadIdx.x;
    float v = x[row * H_DIM + t];

    __shared__ float sh1[4], sh2[4];
    float s = v;
    #pragma unroll
    for (int o = 16; o; o >>= 1) s += __shfl_xor_sync(0xffffffffu, s, o);
    if ((t & 31) == 0) sh1[t >> 5] = s;
    __syncthreads();
    float mean = (sh1[0] + sh1[1] + sh1[2] + sh1[3]) * (1.f / 128.f);

    float d = v - mean;
    float q = d * d;
    #pragma unroll
    for (int o = 16; o; o >>= 1) q += __shfl_xor_sync(0xffffffffu, q, o);
    if ((t & 31) == 0) sh2[t >> 5] = q;
    __syncthreads();
    float var = (sh2[0] + sh2[1] + sh2[2] + sh2[3]) * (1.f / 128.f);

    out[row * H_DIM + t] = d * rsqrtf(var + 1e-5f) * sc[t] + bi[t];
}

// ---------------- sparse attention: 4 lanes per (query, head) ----------------
// 256 threads/block = 64 (q,h) groups. Lane j of group handles neighbors j, j+4, ...
__global__ __launch_bounds__(256)
void attn_sparse4_kernel(const float* __restrict__ qkv, float* __restrict__ o) {
    int gid  = blockIdx.x * 256 + threadIdx.x;
    int grp  = gid >> 2;          // (q,h) index
    int lane = gid & 3;
    int q = grp >> 3;
    int h = grp & 7;

    const float* qp = qkv + (size_t)q * 384 + h * HD;
    float4 q0 = *(const float4*)(qp);
    float4 q1 = *(const float4*)(qp + 4);
    float4 q2 = *(const float4*)(qp + 8);
    float4 q3 = *(const float4*)(qp + 12);

    int cnt = g_ncnt[q];
    const int* nb = &g_nbr[q * CAP];

    float m = -1e30f, l = 0.f;
    float acc[HD];
    #pragma unroll
    for (int d = 0; d < HD; d++) acc[d] = 0.f;

    for (int j = lane; j < cnt; j += 4) {
        int kidx = nb[j];
        const float* kp = qkv + (size_t)kidx * 384 + 128 + h * HD;
        float4 k0 = *(const float4*)(kp);
        float4 k1 = *(const float4*)(kp + 4);
        float4 k2 = *(const float4*)(kp + 8);
        float4 k3 = *(const float4*)(kp + 12);
        float s = q0.x * k0.x + q0.y * k0.y + q0.z * k0.z + q0.w * k0.w
                + q1.x * k1.x + q1.y * k1.y + q1.z * k1.z + q1.w * k1.w
                + q2.x * k2.x + q2.y * k2.y + q2.z * k2.z + q2.w * k2.w
                + q3.x * k3.x + q3.y * k3.y + q3.z * k3.z + q3.w * k3.w;
        s *= 0.25f;
        float mnew = fmaxf(m, s);
        float corr = __expf(m - mnew);
        float e    = __expf(s - mnew);
        l = l * corr + e;
        const float* vp = kp + 128;
        float4 v0 = *(const float4*)(vp);
        float4 v1 = *(const float4*)(vp + 4);
        float4 v2 = *(const float4*)(vp + 8);
        float4 v3 = *(const float4*)(vp + 12);
        acc[0]  = acc[0]  * corr + e * v0.x;  acc[1]  = acc[1]  * corr + e * v0.y;
        acc[2]  = acc[2]  * corr + e * v0.z;  acc[3]  = acc[3]  * corr + e * v0.w;
        acc[4]  = acc[4]  * corr + e * v1.x;  acc[5]  = acc[5]  * corr + e * v1.y;
        acc[6]  = acc[6]  * corr + e * v1.z;  acc[7]  = acc[7]  * corr + e * v1.w;
        acc[8]  = acc[8]  * corr + e * v2.x;  acc[9]  = acc[9]  * corr + e * v2.y;
        acc[10] = acc[10] * corr + e * v2.z;  acc[11] = acc[11] * corr + e * v2.w;
        acc[12] = acc[12] * corr + e * v3.x;  acc[13] = acc[13] * corr + e * v3.y;
        acc[14] = acc[14] * corr + e * v3.z;  acc[15] = acc[15] * corr + e * v3.w;
        m = mnew;
    }

    // symmetric merge across the 4 lanes of this group (xor 1, then xor 2)
    #pragma unroll
    for (int off = 1; off <= 2; off <<= 1) {
        float mo = __shfl_xor_sync(0xffffffffu, m, off);
        float lo = __shfl_xor_sync(0xffffffffu, l, off);
        float mm = fmaxf(m, mo);
        float ca = __expf(m  - mm);
        float cb = __expf(mo - mm);
        l = l * ca + lo * cb;
        #pragma unroll
        for (int d = 0; d < HD; d++) {
            float ao = __shfl_xor_sync(0xffffffffu, acc[d], off);
            acc[d] = acc[d] * ca + ao * cb;
        }
        m = mm;
    }

    float inv = 1.f / l;
    float* op = o + (size_t)q * H_DIM + h * HD;
    #pragma unroll
    for (int dd = 0; dd < 4; dd++) {
        int d = lane * 4 + dd;
        op[d] = acc[d] * inv;
    }
}

// ---------------- fused heads: lat + beta + epilogue ----------------
__global__ __launch_bounds__(128)
void head_kernel(const float* __restrict__ x,
                 const float* __restrict__ lat1_w, const float* __restrict__ lat1_b,
                 const float* __restrict__ lat2_w, const float* __restrict__ lat2_b,
                 const float* __restrict__ b1_w,   const float* __restrict__ b1_b,
                 const float* __restrict__ b2_w,   const float* __restrict__ b2_b,
                 float* __restrict__ out) {
    __shared__ float Xs[32][132];
    __shared__ float H1[32][132];
    __shared__ float Lt[32][20];
    __shared__ float B1[32][68];

    const int tid  = threadIdx.x;
    const int row0 = blockIdx.x * 32;
    const int r    = tid >> 2;
    const int q    = tid & 3;

    #pragma unroll
    for (int t = 0; t < 8; t++) {
        int i  = tid + t * 128;
        int rr = i >> 5;
        int c  = (i & 31) * 4;
        float4 v = *(const float4*)(x + (size_t)(row0 + rr) * H_DIM + c);
        Xs[rr][c] = v.x; Xs[rr][c + 1] = v.y; Xs[rr][c + 2] = v.z; Xs[rr][c + 3] = v.w;
    }
    __syncthreads();

    #pragma unroll 1
    for (int c = 0; c < 32; c++) {
        int col = q * 32 + c;
        const float* wp = lat1_w + (size_t)col * H_DIM;
        float s = lat1_b[col];
        #pragma unroll 8
        for (int k = 0; k < H_DIM; k++) s += Xs[r][k] * wp[k];
        H1[r][col] = fmaxf(s, 0.f);
    }
    #pragma unroll 1
    for (int c = 0; c < 16; c++) {
        int col = q * 16 + c;
        const float* wp = b1_w + (size_t)col * H_DIM;
        float s = b1_b[col];
        #pragma unroll 8
        for (int k = 0; k < H_DIM; k++) s += Xs[r][k] * wp[k];
        B1[r][col] = fmaxf(s, 0.f);
    }
    __syncthreads();

    #pragma unroll
    for (int c = 0; c < 4; c++) {
        int col = q * 4 + c;
        const float* wp = lat2_w + (size_t)col * H_DIM;
        float s = lat2_b[col];
        #pragma unroll 8
        for (int k = 0; k < H_DIM; k++) s += H1[r][k] * wp[k];
        Lt[r][col] = s;
    }
    __syncthreads();

    if (tid < 32) {
        int rr = tid;
        float s = b2_b[0];
        #pragma unroll 8
        for (int k = 0; k < 64; k++) s += B1[rr][k] * b2_w[k];
        float bb = 1.f / (1.f + __expf(-s));
        bb = fminf(fmaxf(bb, 1e-6f), 1.f - 1e-6f);
        out[row0 + rr] = bb;

        float nn = 0.f;
        #pragma unroll
        for (int d = 0; d < LAT_DIM; d++) nn += Lt[rr][d] * Lt[rr][d];
        float inv = 1.f / fmaxf(sqrtf(nn), 1e-12f);
        #pragma unroll
        for (int d = 0; d < LAT_DIM; d++)
            out[N_TOK + (size_t)(row0 + rr) * LAT_DIM + d] = Lt[rr][d] * inv;
    }
}

// ---------------- host orchestration ----------------
extern "C" void kernel_launch(void* const* d_in, const int* in_sizes, int n_in,
                              void* d_out, int out_size) {
    const float* x_raw  = (const float*)d_in[0];
    const float* in_w   = (const float*)d_in[2];
    const float* in_b   = (const float*)d_in[3];
    const float* ln1_s  = (const float*)d_in[4];
    const float* ln1_b  = (const float*)d_in[5];
    const float* qkv_w  = (const float*)d_in[6];
    const float* qkv_b  = (const float*)d_in[7];
    const float* ao_w   = (const float*)d_in[8];
    const float* ao_b   = (const float*)d_in[9];
    const float* ln2_s  = (const float*)d_in[10];
    const float* ln2_b  = (const float*)d_in[11];
    const float* f1_w   = (const float*)d_in[12];
    const float* f1_b   = (const float*)d_in[13];
    const float* f2_w   = (const float*)d_in[14];
    const float* f2_b   = (const float*)d_in[15];
    const float* lat1_w = (const float*)d_in[16];
    const float* lat1_b = (const float*)d_in[17];
    const float* lat2_w = (const float*)d_in[18];
    const float* lat2_b = (const float*)d_in[19];
    const float* b1_w   = (const float*)d_in[20];
    const float* b1_b   = (const float*)d_in[21];
    const float* b2_w   = (const float*)d_in[22];
    const float* b2_b   = (const float*)d_in[23];

    float *x, *xn, *qkv, *attn, *tmp;
    cudaGetSymbolAddress((void**)&x,    g_x);
    cudaGetSymbolAddress((void**)&xn,   g_xn);
    cudaGetSymbolAddress((void**)&qkv,  g_qkv);
    cudaGetSymbolAddress((void**)&attn, g_attn);
    cudaGetSymbolAddress((void**)&tmp,  g_tmp);

    dim3 blk(128);

    nbr_kernel<<<N_TOK / 8, 256>>>(x_raw);

    // input projection: K=16, M=128
    gemm2_kernel<<<dim3(N_TOK / GM, H_DIM / GN), blk>>>(
        x_raw, in_w, in_b, nullptr, x, N_TOK, H_DIM, 16, 0);

    for (int l = 0; l < L_LAYER; l++) {
        ln_kernel<<<N_TOK, 128>>>(x, ln1_s + l * H_DIM, ln1_b + l * H_DIM, xn);
        gemm2_kernel<<<dim3(N_TOK / GM, (3 * H_DIM) / GN), blk>>>(
            xn, qkv_w + (size_t)l * 3 * H_DIM * H_DIM, qkv_b + l * 3 * H_DIM,
            nullptr, qkv, N_TOK, 3 * H_DIM, H_DIM, 0);
        attn_sparse4_kernel<<<(N_TOK * NH * 4) / 256, 256>>>(qkv, attn);
        gemm2_kernel<<<dim3(N_TOK / GM, H_DIM / GN), blk>>>(
            attn, ao_w + (size_t)l * H_DIM * H_DIM, ao_b + l * H_DIM,
            x, x, N_TOK, H_DIM, H_DIM, 0);
        ln_kernel<<<N_TOK, 128>>>(x, ln2_s + l * H_DIM, ln2_b + l * H_DIM, xn);
        gemm2_kernel<<<dim3(N_TOK / GM, FF_DIM / GN), blk>>>(
            xn, f1_w + (size_t)l * FF_DIM * H_DIM, f1_b + l * FF_DIM,
            nullptr, tmp, N_TOK, FF_DIM, H_DIM, 1);
        gemm2_kernel<<<dim3(N_TOK / GM, H_DIM / GN), blk>>>(
            tmp, f2_w + (size_t)l * H_DIM * FF_DIM, f2_b + l * H_DIM,
            x, x, N_TOK, H_DIM, FF_DIM, 0);
    }

    head_kernel<<<N_TOK / 32, 128>>>(x, lat1_w, lat1_b, lat2_w, lat2_b,
                                     b1_w, b1_b, b2_w, b2_b, (float*)d_out);
}

// round 6
// speedup vs baseline: 1.5769x; 1.3313x over previous
#include <cuda_runtime.h>
#include <math.h>

#define N_TOK   4096
#define H_DIM   128
#define NH      8
#define HD      16
#define FF_DIM  256
#define L_LAYER 4
#define LAT_DIM 16
#define CAP     128

// ---------------- scratch (static device globals; no runtime alloc) ----------------
__device__ __align__(256) float g_x   [N_TOK * H_DIM];
__device__ __align__(256) float g_xn  [N_TOK * H_DIM];
__device__ __align__(256) float g_qkv [N_TOK * 3 * H_DIM];
__device__ __align__(256) float g_attn[N_TOK * H_DIM];
__device__ __align__(256) float g_tmp [N_TOK * FF_DIM];
__device__ __align__(256) float g_eta [N_TOK];
__device__ __align__(256) float g_phi [N_TOK];
__device__ __align__(256) float g_lat [N_TOK * LAT_DIM];
__device__ __align__(256) float g_beta[N_TOK];
__device__ __align__(256) int   g_nbr [N_TOK * CAP];
__device__ __align__(256) int   g_ncnt[N_TOK];

// ---------------- eta/phi precompute ----------------
__global__ void etaphi_kernel(const float* __restrict__ x_raw) {
    int i = blockIdx.x * blockDim.x + threadIdx.x;
    if (i >= N_TOK) return;
    g_eta[i] = x_raw[i * 16 + 1] * 5.24f   + (-2.62f);
    g_phi[i] = x_raw[i * 16 + 2] * 6.2832f + (-3.1416f);
}

// ---------------- neighbor list build: one warp per query ----------------
__global__ __launch_bounds__(256)
void nbr_kernel() {
    int warp = (blockIdx.x * blockDim.x + threadIdx.x) >> 5;
    int lane = threadIdx.x & 31;
    if (warp >= N_TOK) return;
    float eq = g_eta[warp], pq = g_phi[warp];
    int cnt = 0;
    for (int k = lane; k < N_TOK; k += 32) {
        float de = eq - g_eta[k];
        float dp = pq - g_phi[k];
        dp -= 6.28318530718f * rintf(dp * 0.159154943092f);
        bool hit = (de * de + dp * dp) <= 0.04f;
        unsigned mask = __ballot_sync(0xffffffffu, hit);
        if (hit) {
            int off = cnt + __popc(mask & ((1u << lane) - 1u));
            if (off < CAP) g_nbr[warp * CAP + off] = k;
        }
        cnt += __popc(mask);
    }
    if (lane == 0) g_ncnt[warp] = min(cnt, CAP);
}

// ---------------- register-tiled GEMM: 64x64x16, 128 threads, 8x4/thread -----------
#define GM 64
#define GN 64
#define GK 16
#define GMP 68   // 272B row pitch, 16B multiple -> aligned LDS.128 for any k

__global__ __launch_bounds__(128)
void gemm2_kernel(const float* __restrict__ A, const float* __restrict__ W,
                  const float* __restrict__ bias, const float* __restrict__ res,
                  float* __restrict__ C, int N, int M, int K, int relu) {
    __shared__ __align__(16) float As[GK][GMP];
    __shared__ __align__(16) float Ws[GK][GMP];

    const int tid  = threadIdx.x;
    const int row0 = blockIdx.x * GM;
    const int col0 = blockIdx.y * GN;
    const int tx   = tid & 15;
    const int ty   = tid >> 4;

    float acc[8][4];
    #pragma unroll
    for (int i = 0; i < 8; i++)
        #pragma unroll
        for (int j = 0; j < 4; j++) acc[i][j] = 0.f;

    for (int k0 = 0; k0 < K; k0 += GK) {
        #pragma unroll
        for (int t = 0; t < 2; t++) {
            int i = tid + t * 128;
            int r = i >> 2, kq = (i & 3) << 2;
            int gr = row0 + r;
            float4 v = make_float4(0.f, 0.f, 0.f, 0.f);
            if (gr < N) v = *(const float4*)(A + (size_t)gr * K + k0 + kq);
            As[kq + 0][r] = v.x; As[kq + 1][r] = v.y;
            As[kq + 2][r] = v.z; As[kq + 3][r] = v.w;
        }
        #pragma unroll
        for (int t = 0; t < 2; t++) {
            int i = tid + t * 128;
            int r = i >> 2, kq = (i & 3) << 2;
            int gm = col0 + r;
            float4 v = make_float4(0.f, 0.f, 0.f, 0.f);
            if (gm < M) v = *(const float4*)(W + (size_t)gm * K + k0 + kq);
            Ws[kq + 0][r] = v.x; Ws[kq + 1][r] = v.y;
            Ws[kq + 2][r] = v.z; Ws[kq + 3][r] = v.w;
        }
        __syncthreads();
        #pragma unroll
        for (int k = 0; k < GK; k++) {
            float a[8], b[4];
            *(float4*)(a)     = *(const float4*)&As[k][ty * 8];
            *(float4*)(a + 4) = *(const float4*)&As[k][ty * 8 + 4];
            *(float4*)(b)     = *(const float4*)&Ws[k][tx * 4];
            #pragma unroll
            for (int i = 0; i < 8; i++)
                #pragma unroll
                for (int j = 0; j < 4; j++)
                    acc[i][j] += a[i] * b[j];
        }
        __syncthreads();
    }

    #pragma unroll
    for (int i = 0; i < 8; i++) {
        int gr = row0 + ty * 8 + i;
        if (gr >= N) continue;
        #pragma unroll
        for (int j = 0; j < 4; j++) {
            int gm = col0 + tx * 4 + j;
            if (gm >= M) continue;
            float v = acc[i][j] + bias[gm];
            if (res)  v += res[(size_t)gr * M + gm];
            if (relu) v = fmaxf(v, 0.f);
            C[(size_t)gr * M + gm] = v;
        }
    }
}

// ---------------- LayerNorm: one row per block (128 threads) ----------------
__global__ __launch_bounds__(128)
void ln_kernel(const float* __restrict__ x, const float* __restrict__ sc,
               const float* __restrict__ bi, float* __restrict__ out) {
    const int row = blockIdx.x;
    const int t   = threadIdx.x;
    float v = x[row * H_DIM + t];

    __shared__ float sh1[4], sh2[4];
    float s = v;
    #pragma unroll
    for (int o = 16; o; o >>= 1) s += __shfl_xor_sync(0xffffffffu, s, o);
    if ((t & 31) == 0) sh1[t >> 5] = s;
    __syncthreads();
    float mean = (sh1[0] + sh1[1] + sh1[2] + sh1[3]) * (1.f / 128.f);

    float d = v - mean;
    float q = d * d;
    #pragma unroll
    for (int o = 16; o; o >>= 1) q += __shfl_xor_sync(0xffffffffu, q, o);
    if ((t & 31) == 0) sh2[t >> 5] = q;
    __syncthreads();
    float var = (sh2[0] + sh2[1] + sh2[2] + sh2[3]) * (1.f / 128.f);

    out[row * H_DIM + t] = d * rsqrtf(var + 1e-5f) * sc[t] + bi[t];
}

// ---------------- sparse attention: 4 lanes per (query, head) ----------------
__global__ __launch_bounds__(256)
void attn_sparse4_kernel(const float* __restrict__ qkv, float* __restrict__ o) {
    int gid  = blockIdx.x * 256 + threadIdx.x;
    int grp  = gid >> 2;          // (q,h) index
    int lane = gid & 3;
    int q = grp >> 3;
    int h = grp & 7;

    const float* qp = qkv + (size_t)q * 384 + h * HD;
    float4 q0 = *(const float4*)(qp);
    float4 q1 = *(const float4*)(qp + 4);
    float4 q2 = *(const float4*)(qp + 8);
    float4 q3 = *(const float4*)(qp + 12);

    int cnt = g_ncnt[q];
    const int* nb = &g_nbr[q * CAP];

    float m = -1e30f, l = 0.f;
    float acc[HD];
    #pragma unroll
    for (int d = 0; d < HD; d++) acc[d] = 0.f;

    for (int j = lane; j < cnt; j += 4) {
        int kidx = nb[j];
        const float* kp = qkv + (size_t)kidx * 384 + 128 + h * HD;
        float4 k0 = *(const float4*)(kp);
        float4 k1 = *(const float4*)(kp + 4);
        float4 k2 = *(const float4*)(kp + 8);
        float4 k3 = *(const float4*)(kp + 12);
        float s = q0.x * k0.x + q0.y * k0.y + q0.z * k0.z + q0.w * k0.w
                + q1.x * k1.x + q1.y * k1.y + q1.z * k1.z + q1.w * k1.w
                + q2.x * k2.x + q2.y * k2.y + q2.z * k2.z + q2.w * k2.w
                + q3.x * k3.x + q3.y * k3.y + q3.z * k3.z + q3.w * k3.w;
        s *= 0.25f;
        float mnew = fmaxf(m, s);
        float corr = __expf(m - mnew);
        float e    = __expf(s - mnew);
        l = l * corr + e;
        const float* vp = kp + 128;
        float4 v0 = *(const float4*)(vp);
        float4 v1 = *(const float4*)(vp + 4);
        float4 v2 = *(const float4*)(vp + 8);
        float4 v3 = *(const float4*)(vp + 12);
        acc[0]  = acc[0]  * corr + e * v0.x;  acc[1]  = acc[1]  * corr + e * v0.y;
        acc[2]  = acc[2]  * corr + e * v0.z;  acc[3]  = acc[3]  * corr + e * v0.w;
        acc[4]  = acc[4]  * corr + e * v1.x;  acc[5]  = acc[5]  * corr + e * v1.y;
        acc[6]  = acc[6]  * corr + e * v1.z;  acc[7]  = acc[7]  * corr + e * v1.w;
        acc[8]  = acc[8]  * corr + e * v2.x;  acc[9]  = acc[9]  * corr + e * v2.y;
        acc[10] = acc[10] * corr + e * v2.z;  acc[11] = acc[11] * corr + e * v2.w;
        acc[12] = acc[12] * corr + e * v3.x;  acc[13] = acc[13] * corr + e * v3.y;
        acc[14] = acc[14] * corr + e * v3.z;  acc[15] = acc[15] * corr + e * v3.w;
        m = mnew;
    }

    // symmetric merge across the 4 lanes of this group (xor 1, then xor 2)
    #pragma unroll
    for (int off = 1; off <= 2; off <<= 1) {
        float mo = __shfl_xor_sync(0xffffffffu, m, off);
        float lo = __shfl_xor_sync(0xffffffffu, l, off);
        float mm = fmaxf(m, mo);
        float ca = __expf(m  - mm);
        float cb = __expf(mo - mm);
        l = l * ca + lo * cb;
        #pragma unroll
        for (int d = 0; d < HD; d++) {
            float ao = __shfl_xor_sync(0xffffffffu, acc[d], off);
            acc[d] = acc[d] * ca + ao * cb;
        }
        m = mm;
    }

    float inv = 1.f / l;
    float* op = o + (size_t)q * H_DIM + h * HD;
    #pragma unroll
    for (int dd = 0; dd < 4; dd++) {
        int d = lane * 4 + dd;
        op[d] = acc[d] * inv;
    }
}

// ---------------- heads epilogue ----------------
__global__ void final_kernel(float* __restrict__ out) {
    int i = blockIdx.x * blockDim.x + threadIdx.x;
    if (i >= N_TOK) return;
    float bb = 1.f / (1.f + __expf(-g_beta[i]));
    bb = fminf(fmaxf(bb, 1e-6f), 1.f - 1e-6f);
    out[i] = bb;
    float nn = 0.f;
    float lv[LAT_DIM];
    #pragma unroll
    for (int d = 0; d < LAT_DIM; d++) { lv[d] = g_lat[i * LAT_DIM + d]; nn += lv[d] * lv[d]; }
    float inv = 1.f / fmaxf(sqrtf(nn), 1e-12f);
    #pragma unroll
    for (int d = 0; d < LAT_DIM; d++) out[N_TOK + i * LAT_DIM + d] = lv[d] * inv;
}

// ---------------- host orchestration ----------------
extern "C" void kernel_launch(void* const* d_in, const int* in_sizes, int n_in,
                              void* d_out, int out_size) {
    const float* x_raw  = (const float*)d_in[0];
    const float* in_w   = (const float*)d_in[2];
    const float* in_b   = (const float*)d_in[3];
    const float* ln1_s  = (const float*)d_in[4];
    const float* ln1_b  = (const float*)d_in[5];
    const float* qkv_w  = (const float*)d_in[6];
    const float* qkv_b  = (const float*)d_in[7];
    const float* ao_w   = (const float*)d_in[8];
    const float* ao_b   = (const float*)d_in[9];
    const float* ln2_s  = (const float*)d_in[10];
    const float* ln2_b  = (const float*)d_in[11];
    const float* f1_w   = (const float*)d_in[12];
    const float* f1_b   = (const float*)d_in[13];
    const float* f2_w   = (const float*)d_in[14];
    const float* f2_b   = (const float*)d_in[15];
    const float* lat1_w = (const float*)d_in[16];
    const float* lat1_b = (const float*)d_in[17];
    const float* lat2_w = (const float*)d_in[18];
    const float* lat2_b = (const float*)d_in[19];
    const float* b1_w   = (const float*)d_in[20];
    const float* b1_b   = (const float*)d_in[21];
    const float* b2_w   = (const float*)d_in[22];
    const float* b2_b   = (const float*)d_in[23];

    float *x, *xn, *qkv, *attn, *tmp, *lat, *beta;
    cudaGetSymbolAddress((void**)&x,    g_x);
    cudaGetSymbolAddress((void**)&xn,   g_xn);
    cudaGetSymbolAddress((void**)&qkv,  g_qkv);
    cudaGetSymbolAddress((void**)&attn, g_attn);
    cudaGetSymbolAddress((void**)&tmp,  g_tmp);
    cudaGetSymbolAddress((void**)&lat,  g_lat);
    cudaGetSymbolAddress((void**)&beta, g_beta);

    dim3 blk(128);

    etaphi_kernel<<<(N_TOK + 255) / 256, 256>>>(x_raw);
    nbr_kernel<<<N_TOK / 8, 256>>>();

    // input projection: K=16, M=128
    gemm2_kernel<<<dim3(N_TOK / GM, H_DIM / GN), blk>>>(
        x_raw, in_w, in_b, nullptr, x, N_TOK, H_DIM, 16, 0);

    for (int l = 0; l < L_LAYER; l++) {
        ln_kernel<<<N_TOK, 128>>>(x, ln1_s + l * H_DIM, ln1_b + l * H_DIM, xn);
        gemm2_kernel<<<dim3(N_TOK / GM, (3 * H_DIM) / GN), blk>>>(
            xn, qkv_w + (size_t)l * 3 * H_DIM * H_DIM, qkv_b + l * 3 * H_DIM,
            nullptr, qkv, N_TOK, 3 * H_DIM, H_DIM, 0);
        attn_sparse4_kernel<<<(N_TOK * NH * 4) / 256, 256>>>(qkv, attn);
        gemm2_kernel<<<dim3(N_TOK / GM, H_DIM / GN), blk>>>(
            attn, ao_w + (size_t)l * H_DIM * H_DIM, ao_b + l * H_DIM,
            x, x, N_TOK, H_DIM, H_DIM, 0);
        ln_kernel<<<N_TOK, 128>>>(x, ln2_s + l * H_DIM, ln2_b + l * H_DIM, xn);
        gemm2_kernel<<<dim3(N_TOK / GM, FF_DIM / GN), blk>>>(
            xn, f1_w + (size_t)l * FF_DIM * H_DIM, f1_b + l * FF_DIM,
            nullptr, tmp, N_TOK, FF_DIM, H_DIM, 1);
        gemm2_kernel<<<dim3(N_TOK / GM, H_DIM / GN), blk>>>(
            tmp, f2_w + (size_t)l * H_DIM * FF_DIM, f2_b + l * H_DIM,
            x, x, N_TOK, H_DIM, FF_DIM, 0);
    }

    gemm2_kernel<<<dim3(N_TOK / GM, H_DIM / GN), blk>>>(
        x, lat1_w, lat1_b, nullptr, xn, N_TOK, H_DIM, H_DIM, 1);
    gemm2_kernel<<<dim3(N_TOK / GM, 1), blk>>>(
        xn, lat2_w, lat2_b, nullptr, lat, N_TOK, LAT_DIM, H_DIM, 0);

    gemm2_kernel<<<dim3(N_TOK / GM, 1), blk>>>(
        x, b1_w, b1_b, nullptr, tmp, N_TOK, H_DIM / 2, H_DIM, 1);
    gemm2_kernel<<<dim3(N_TOK / GM, 1), blk>>>(
        tmp, b2_w, b2_b, nullptr, beta, N_TOK, 1, H_DIM / 2, 0);

    final_kernel<<<(N_TOK + 255) / 256, 256>>>((float*)d_out);
}

// round 7
// speedup vs baseline: 1.9074x; 1.2096x over previous
#include <cuda_runtime.h>
#include <math.h>

#define N_TOK   4096
#define H_DIM   128
#define NH      8
#define HD      16
#define FF_DIM  256
#define L_LAYER 4
#define LAT_DIM 16
#define CAP     128

// ---------------- scratch (static device globals; no runtime alloc) ----------------
__device__ __align__(256) float g_x   [N_TOK * H_DIM];
__device__ __align__(256) float g_xn  [N_TOK * H_DIM];
__device__ __align__(256) float g_qkv [N_TOK * 3 * H_DIM];
__device__ __align__(256) float g_attn[N_TOK * H_DIM];
__device__ __align__(256) float g_tmp [N_TOK * FF_DIM];
__device__ __align__(256) float g_eta [N_TOK];
__device__ __align__(256) float g_phi [N_TOK];
__device__ __align__(256) float g_lat [N_TOK * LAT_DIM];
__device__ __align__(256) float g_beta[N_TOK];
__device__ __align__(256) int   g_nbr [N_TOK * CAP];
__device__ __align__(256) int   g_ncnt[N_TOK];

// ---------------- eta/phi precompute ----------------
__global__ void etaphi_kernel(const float* __restrict__ x_raw) {
    int i = blockIdx.x * blockDim.x + threadIdx.x;
    if (i >= N_TOK) return;
    g_eta[i] = x_raw[i * 16 + 1] * 5.24f   + (-2.62f);
    g_phi[i] = x_raw[i * 16 + 2] * 6.2832f + (-3.1416f);
}

// ---------------- neighbor list build: one warp per query, smem-staged eta/phi -----
__global__ __launch_bounds__(256)
void nbr_kernel() {
    __shared__ float se[N_TOK];
    __shared__ float sp[N_TOK];
    const int tid = threadIdx.x;
    #pragma unroll
    for (int t = 0; t < N_TOK / 256; t++) {
        int i = tid + t * 256;
        se[i] = g_eta[i];
        sp[i] = g_phi[i];
    }
    __syncthreads();

    const int lane = tid & 31;
    const int q    = blockIdx.x * 8 + (tid >> 5);
    const float eq = se[q], pq = sp[q];
    int cnt = 0;
    for (int k = lane; k < N_TOK; k += 32) {
        float de = eq - se[k];
        float dp = pq - sp[k];
        dp -= 6.28318530718f * rintf(dp * 0.159154943092f);
        bool hit = (de * de + dp * dp) <= 0.04f;
        unsigned mask = __ballot_sync(0xffffffffu, hit);
        if (hit) {
            int off = cnt + __popc(mask & ((1u << lane) - 1u));
            if (off < CAP) g_nbr[q * CAP + off] = k;
        }
        cnt += __popc(mask);
    }
    if (lane == 0) g_ncnt[q] = min(cnt, CAP);
}

// ---------------- double-buffered register-tiled GEMM: 64x64x16, 128 thr, 8x4 ------
#define GM 64
#define GN 64
#define GK 16
#define GMP 68   // 272B row pitch, 16B multiple -> aligned LDS.128 for any k

__global__ __launch_bounds__(128)
void gemm2_kernel(const float* __restrict__ A, const float* __restrict__ W,
                  const float* __restrict__ bias, const float* __restrict__ res,
                  float* __restrict__ C, int N, int M, int K, int relu) {
    __shared__ __align__(16) float As[2][GK][GMP];
    __shared__ __align__(16) float Ws[2][GK][GMP];

    const int tid  = threadIdx.x;
    const int row0 = blockIdx.x * GM;
    const int col0 = blockIdx.y * GN;
    const int tx   = tid & 15;
    const int ty   = tid >> 4;

    // per-thread staging coordinates (2 float4 each for A and W)
    const int r0 = tid >> 2;                 // 0..31
    const int r1 = r0 + 32;                  // 32..63
    const int kq = (tid & 3) << 2;           // 0,4,8,12

    float4 pa0, pa1, pw0, pw1;

    // prologue: load k-tile 0
    {
        int ga0 = row0 + r0, ga1 = row0 + r1;
        pa0 = (ga0 < N) ? *(const float4*)(A + (size_t)ga0 * K + kq) : make_float4(0,0,0,0);
        pa1 = (ga1 < N) ? *(const float4*)(A + (size_t)ga1 * K + kq) : make_float4(0,0,0,0);
        int gw0 = col0 + r0, gw1 = col0 + r1;
        pw0 = (gw0 < M) ? *(const float4*)(W + (size_t)gw0 * K + kq) : make_float4(0,0,0,0);
        pw1 = (gw1 < M) ? *(const float4*)(W + (size_t)gw1 * K + kq) : make_float4(0,0,0,0);
    }
    As[0][kq + 0][r0] = pa0.x; As[0][kq + 1][r0] = pa0.y;
    As[0][kq + 2][r0] = pa0.z; As[0][kq + 3][r0] = pa0.w;
    As[0][kq + 0][r1] = pa1.x; As[0][kq + 1][r1] = pa1.y;
    As[0][kq + 2][r1] = pa1.z; As[0][kq + 3][r1] = pa1.w;
    Ws[0][kq + 0][r0] = pw0.x; Ws[0][kq + 1][r0] = pw0.y;
    Ws[0][kq + 2][r0] = pw0.z; Ws[0][kq + 3][r0] = pw0.w;
    Ws[0][kq + 0][r1] = pw1.x; Ws[0][kq + 1][r1] = pw1.y;
    Ws[0][kq + 2][r1] = pw1.z; Ws[0][kq + 3][r1] = pw1.w;
    __syncthreads();

    float acc[8][4];
    #pragma unroll
    for (int i = 0; i < 8; i++)
        #pragma unroll
        for (int j = 0; j < 4; j++) acc[i][j] = 0.f;

    const int nk = K / GK;
    for (int t = 0; t < nk; t++) {
        int buf = t & 1;
        // prefetch next k-tile into registers (overlaps with compute below)
        if (t + 1 < nk) {
            int koff = (t + 1) * GK + kq;
            int ga0 = row0 + r0, ga1 = row0 + r1;
            pa0 = (ga0 < N) ? *(const float4*)(A + (size_t)ga0 * K + koff) : make_float4(0,0,0,0);
            pa1 = (ga1 < N) ? *(const float4*)(A + (size_t)ga1 * K + koff) : make_float4(0,0,0,0);
            int gw0 = col0 + r0, gw1 = col0 + r1;
            pw0 = (gw0 < M) ? *(const float4*)(W + (size_t)gw0 * K + koff) : make_float4(0,0,0,0);
            pw1 = (gw1 < M) ? *(const float4*)(W + (size_t)gw1 * K + koff) : make_float4(0,0,0,0);
        }

        #pragma unroll
        for (int k = 0; k < GK; k++) {
            float a[8], b[4];
            *(float4*)(a)     = *(const float4*)&As[buf][k][ty * 8];
            *(float4*)(a + 4) = *(const float4*)&As[buf][k][ty * 8 + 4];
            *(float4*)(b)     = *(const float4*)&Ws[buf][k][tx * 4];
            #pragma unroll
            for (int i = 0; i < 8; i++)
                #pragma unroll
                for (int j = 0; j < 4; j++)
                    acc[i][j] += a[i] * b[j];
        }

        if (t + 1 < nk) {
            int nb = buf ^ 1;
            As[nb][kq + 0][r0] = pa0.x; As[nb][kq + 1][r0] = pa0.y;
            As[nb][kq + 2][r0] = pa0.z; As[nb][kq + 3][r0] = pa0.w;
            As[nb][kq + 0][r1] = pa1.x; As[nb][kq + 1][r1] = pa1.y;
            As[nb][kq + 2][r1] = pa1.z; As[nb][kq + 3][r1] = pa1.w;
            Ws[nb][kq + 0][r0] = pw0.x; Ws[nb][kq + 1][r0] = pw0.y;
            Ws[nb][kq + 2][r0] = pw0.z; Ws[nb][kq + 3][r0] = pw0.w;
            Ws[nb][kq + 0][r1] = pw1.x; Ws[nb][kq + 1][r1] = pw1.y;
            Ws[nb][kq + 2][r1] = pw1.z; Ws[nb][kq + 3][r1] = pw1.w;
            __syncthreads();
        }
    }

    #pragma unroll
    for (int i = 0; i < 8; i++) {
        int gr = row0 + ty * 8 + i;
        if (gr >= N) continue;
        #pragma unroll
        for (int j = 0; j < 4; j++) {
            int gm = col0 + tx * 4 + j;
            if (gm >= M) continue;
            float v = acc[i][j] + bias[gm];
            if (res)  v += res[(size_t)gr * M + gm];
            if (relu) v = fmaxf(v, 0.f);
            C[(size_t)gr * M + gm] = v;
        }
    }
}

// ---------------- LayerNorm: one warp per row, 8 rows per 256-thread block ---------
__global__ __launch_bounds__(256)
void ln_kernel(const float* __restrict__ x, const float* __restrict__ sc,
               const float* __restrict__ bi, float* __restrict__ out) {
    const int row  = blockIdx.x * 8 + (threadIdx.x >> 5);
    const int lane = threadIdx.x & 31;

    float4 v = *(const float4*)(x + (size_t)row * H_DIM + lane * 4);
    float s  = v.x + v.y + v.z + v.w;
    float s2 = v.x * v.x + v.y * v.y + v.z * v.z + v.w * v.w;
    #pragma unroll
    for (int o = 16; o; o >>= 1) {
        s  += __shfl_xor_sync(0xffffffffu, s,  o);
        s2 += __shfl_xor_sync(0xffffffffu, s2, o);
    }
    float mean = s * (1.f / 128.f);
    float var  = s2 * (1.f / 128.f) - mean * mean;
    float inv  = rsqrtf(var + 1e-5f);

    float4 sc4 = *(const float4*)(sc + lane * 4);
    float4 bi4 = *(const float4*)(bi + lane * 4);
    float4 o4;
    o4.x = (v.x - mean) * inv * sc4.x + bi4.x;
    o4.y = (v.y - mean) * inv * sc4.y + bi4.y;
    o4.z = (v.z - mean) * inv * sc4.z + bi4.z;
    o4.w = (v.w - mean) * inv * sc4.w + bi4.w;
    *(float4*)(out + (size_t)row * H_DIM + lane * 4) = o4;
}

// ---------------- sparse attention: 4 lanes per (query, head) ----------------
__global__ __launch_bounds__(256)
void attn_sparse4_kernel(const float* __restrict__ qkv, float* __restrict__ o) {
    int gid  = blockIdx.x * 256 + threadIdx.x;
    int grp  = gid >> 2;          // (q,h) index
    int lane = gid & 3;
    int q = grp >> 3;
    int h = grp & 7;

    const float* qp = qkv + (size_t)q * 384 + h * HD;
    float4 q0 = *(const float4*)(qp);
    float4 q1 = *(const float4*)(qp + 4);
    float4 q2 = *(const float4*)(qp + 8);
    float4 q3 = *(const float4*)(qp + 12);

    int cnt = g_ncnt[q];
    const int* nb = &g_nbr[q * CAP];

    float m = -1e30f, l = 0.f;
    float acc[HD];
    #pragma unroll
    for (int d = 0; d < HD; d++) acc[d] = 0.f;

    for (int j = lane; j < cnt; j += 4) {
        int kidx = nb[j];
        const float* kp = qkv + (size_t)kidx * 384 + 128 + h * HD;
        float4 k0 = *(const float4*)(kp);
        float4 k1 = *(const float4*)(kp + 4);
        float4 k2 = *(const float4*)(kp + 8);
        float4 k3 = *(const float4*)(kp + 12);
        float s = q0.x * k0.x + q0.y * k0.y + q0.z * k0.z + q0.w * k0.w
                + q1.x * k1.x + q1.y * k1.y + q1.z * k1.z + q1.w * k1.w
                + q2.x * k2.x + q2.y * k2.y + q2.z * k2.z + q2.w * k2.w
                + q3.x * k3.x + q3.y * k3.y + q3.z * k3.z + q3.w * k3.w;
        s *= 0.25f;
        float mnew = fmaxf(m, s);
        float corr = __expf(m - mnew);
        float e    = __expf(s - mnew);
        l = l * corr + e;
        const float* vp = kp + 128;
        float4 v0 = *(const float4*)(vp);
        float4 v1 = *(const float4*)(vp + 4);
        float4 v2 = *(const float4*)(vp + 8);
        float4 v3 = *(const float4*)(vp + 12);
        acc[0]  = acc[0]  * corr + e * v0.x;  acc[1]  = acc[1]  * corr + e * v0.y;
        acc[2]  = acc[2]  * corr + e * v0.z;  acc[3]  = acc[3]  * corr + e * v0.w;
        acc[4]  = acc[4]  * corr + e * v1.x;  acc[5]  = acc[5]  * corr + e * v1.y;
        acc[6]  = acc[6]  * corr + e * v1.z;  acc[7]  = acc[7]  * corr + e * v1.w;
        acc[8]  = acc[8]  * corr + e * v2.x;  acc[9]  = acc[9]  * corr + e * v2.y;
        acc[10] = acc[10] * corr + e * v2.z;  acc[11] = acc[11] * corr + e * v2.w;
        acc[12] = acc[12] * corr + e * v3.x;  acc[13] = acc[13] * corr + e * v3.y;
        acc[14] = acc[14] * corr + e * v3.z;  acc[15] = acc[15] * corr + e * v3.w;
        m = mnew;
    }

    // symmetric merge across the 4 lanes of this group
    #pragma unroll
    for (int off = 1; off <= 2; off <<= 1) {
        float mo = __shfl_xor_sync(0xffffffffu, m, off);
        float lo = __shfl_xor_sync(0xffffffffu, l, off);
        float mm = fmaxf(m, mo);
        float ca = __expf(m  - mm);
        float cb = __expf(mo - mm);
        l = l * ca + lo * cb;
        #pragma unroll
        for (int d = 0; d < HD; d++) {
            float ao = __shfl_xor_sync(0xffffffffu, acc[d], off);
            acc[d] = acc[d] * ca + ao * cb;
        }
        m = mm;
    }

    float inv = 1.f / l;
    float* op = o + (size_t)q * H_DIM + h * HD;
    #pragma unroll
    for (int dd = 0; dd < 4; dd++) {
        int d = lane * 4 + dd;
        op[d] = acc[d] * inv;
    }
}

// ---------------- heads epilogue ----------------
__global__ void final_kernel(float* __restrict__ out) {
    int i = blockIdx.x * blockDim.x + threadIdx.x;
    if (i >= N_TOK) return;
    float bb = 1.f / (1.f + __expf(-g_beta[i]));
    bb = fminf(fmaxf(bb, 1e-6f), 1.f - 1e-6f);
    out[i] = bb;
    float nn = 0.f;
    float lv[LAT_DIM];
    #pragma unroll
    for (int d = 0; d < LAT_DIM; d++) { lv[d] = g_lat[i * LAT_DIM + d]; nn += lv[d] * lv[d]; }
    float inv = 1.f / fmaxf(sqrtf(nn), 1e-12f);
    #pragma unroll
    for (int d = 0; d < LAT_DIM; d++) out[N_TOK + i * LAT_DIM + d] = lv[d] * inv;
}

// ---------------- host orchestration ----------------
extern "C" void kernel_launch(void* const* d_in, const int* in_sizes, int n_in,
                              void* d_out, int out_size) {
    const float* x_raw  = (const float*)d_in[0];
    const float* in_w   = (const float*)d_in[2];
    const float* in_b   = (const float*)d_in[3];
    const float* ln1_s  = (const float*)d_in[4];
    const float* ln1_b  = (const float*)d_in[5];
    const float* qkv_w  = (const float*)d_in[6];
    const float* qkv_b  = (const float*)d_in[7];
    const float* ao_w   = (const float*)d_in[8];
    const float* ao_b   = (const float*)d_in[9];
    const float* ln2_s  = (const float*)d_in[10];
    const float* ln2_b  = (const float*)d_in[11];
    const float* f1_w   = (const float*)d_in[12];
    const float* f1_b   = (const float*)d_in[13];
    const float* f2_w   = (const float*)d_in[14];
    const float* f2_b   = (const float*)d_in[15];
    const float* lat1_w = (const float*)d_in[16];
    const float* lat1_b = (const float*)d_in[17];
    const float* lat2_w = (const float*)d_in[18];
    const float* lat2_b = (const float*)d_in[19];
    const float* b1_w   = (const float*)d_in[20];
    const float* b1_b   = (const float*)d_in[21];
    const float* b2_w   = (const float*)d_in[22];
    const float* b2_b   = (const float*)d_in[23];

    float *x, *xn, *qkv, *attn, *tmp, *lat, *beta;
    cudaGetSymbolAddress((void**)&x,    g_x);
    cudaGetSymbolAddress((void**)&xn,   g_xn);
    cudaGetSymbolAddress((void**)&qkv,  g_qkv);
    cudaGetSymbolAddress((void**)&attn, g_attn);
    cudaGetSymbolAddress((void**)&tmp,  g_tmp);
    cudaGetSymbolAddress((void**)&lat,  g_lat);
    cudaGetSymbolAddress((void**)&beta, g_beta);

    dim3 blk(128);

    etaphi_kernel<<<(N_TOK + 255) / 256, 256>>>(x_raw);
    nbr_kernel<<<N_TOK / 8, 256>>>();

    // input projection: K=16, M=128
    gemm2_kernel<<<dim3(N_TOK / GM, H_DIM / GN), blk>>>(
        x_raw, in_w, in_b, nullptr, x, N_TOK, H_DIM, 16, 0);

    for (int l = 0; l < L_LAYER; l++) {
        ln_kernel<<<N_TOK / 8, 256>>>(x, ln1_s + l * H_DIM, ln1_b + l * H_DIM, xn);
        gemm2_kernel<<<dim3(N_TOK / GM, (3 * H_DIM) / GN), blk>>>(
            xn, qkv_w + (size_t)l * 3 * H_DIM * H_DIM, qkv_b + l * 3 * H_DIM,
            nullptr, qkv, N_TOK, 3 * H_DIM, H_DIM, 0);
        attn_sparse4_kernel<<<(N_TOK * NH * 4) / 256, 256>>>(qkv, attn);
        gemm2_kernel<<<dim3(N_TOK / GM, H_DIM / GN), blk>>>(
            attn, ao_w + (size_t)l * H_DIM * H_DIM, ao_b + l * H_DIM,
            x, x, N_TOK, H_DIM, H_DIM, 0);
        ln_kernel<<<N_TOK / 8, 256>>>(x, ln2_s + l * H_DIM, ln2_b + l * H_DIM, xn);
        gemm2_kernel<<<dim3(N_TOK / GM, FF_DIM / GN), blk>>>(
            xn, f1_w + (size_t)l * FF_DIM * H_DIM, f1_b + l * FF_DIM,
            nullptr, tmp, N_TOK, FF_DIM, H_DIM, 1);
        gemm2_kernel<<<dim3(N_TOK / GM, H_DIM / GN), blk>>>(
            tmp, f2_w + (size_t)l * H_DIM * FF_DIM, f2_b + l * H_DIM,
            x, x, N_TOK, H_DIM, FF_DIM, 0);
    }

    gemm2_kernel<<<dim3(N_TOK / GM, H_DIM / GN), blk>>>(
        x, lat1_w, lat1_b, nullptr, xn, N_TOK, H_DIM, H_DIM, 1);
    gemm2_kernel<<<dim3(N_TOK / GM, 1), blk>>>(
        xn, lat2_w, lat2_b, nullptr, lat, N_TOK, LAT_DIM, H_DIM, 0);

    gemm2_kernel<<<dim3(N_TOK / GM, 1), blk>>>(
        x, b1_w, b1_b, nullptr, tmp, N_TOK, H_DIM / 2, H_DIM, 1);
    gemm2_kernel<<<dim3(N_TOK / GM, 1), blk>>>(
        tmp, b2_w, b2_b, nullptr, beta, N_TOK, 1, H_DIM / 2, 0);

    final_kernel<<<(N_TOK + 255) / 256, 256>>>((float*)d_out);
}